// round 16
// baseline (speedup 1.0000x reference)
#include <cuda_runtime.h>
#include <cuda_fp16.h>
#include <math.h>
#include <stdint.h>

#define NB   32
#define CC   64
#define LL   1024
#define EPS  1e-6f

// ---------------- scratch (static __device__, no allocation) ----------------
__device__ __half g_ah[NB*LL*CC];                // rgb * (sqrt(10*log2e)/||.||)
__device__ __half g_bh[NB*LL*CC];                // ir  * (sqrt(10*log2e)/||.||)
__device__ unsigned long long g_rkey[8][NB*LL];  // per-eighth row (max,arg) packed
__device__ float              g_rsum[8][NB*LL];  // per-eighth row sums
__device__ unsigned long long g_ckey[8][NB*LL];  // per-panel col (max,arg) packed
__device__ float              g_csum[8][NB*LL];  // per-panel col sums
__device__ float g_part[256];
__device__ unsigned g_cnt;

#define SW128(o) ((o) ^ (((o) >> 3) & 0x70))

__device__ __forceinline__ uint32_t smem_u32(const void* p) {
    uint32_t a;
    asm("{ .reg .u64 t; cvta.to.shared.u64 t, %1; cvt.u32.u64 %0, t; }" : "=r"(a) : "l"(p));
    return a;
}
__device__ __forceinline__ float ex2f(float x) {
    float y; asm("ex2.approx.f32 %0, %1;" : "=f"(y) : "f"(x)); return y;
}
__device__ __forceinline__ void ldmx4(uint32_t* r, uint32_t addr) {
    asm volatile("ldmatrix.sync.aligned.m8n8.x4.shared.b16 {%0,%1,%2,%3}, [%4];"
                 : "=r"(r[0]), "=r"(r[1]), "=r"(r[2]), "=r"(r[3]) : "r"(addr));
}
__device__ __forceinline__ void mma16816(float* d, const uint32_t* a, uint32_t b0, uint32_t b1) {
    asm volatile("mma.sync.aligned.m16n8k16.row.col.f32.f16.f16.f32 "
                 "{%0,%1,%2,%3}, {%4,%5,%6,%7}, {%8,%9}, {%0,%1,%2,%3};"
                 : "+f"(d[0]), "+f"(d[1]), "+f"(d[2]), "+f"(d[3])
                 : "r"(a[0]), "r"(a[1]), "r"(a[2]), "r"(a[3]), "r"(b0), "r"(b1));
}

// ---------------- kernel 1: coalesced normalize+scale+fp16+transpose ---------
// Block: 64 channels x 128 pixels staged via smem (all gmem accesses 128B-coalesced).
// scale folds sqrt(10 * log2(e)) so 2^(dot) == exp(dot_orig / TEMP).
__global__ __launch_bounds__(256) void prep_kernel(
    const float* __restrict__ rgb, const float* __restrict__ ir)
{
    __shared__ float xs[64][132];   // padded: conflict-light column reads

    int z = blockIdx.z;
    const float* src = z ? ir : rgb;
    __half* dst = z ? g_bh : g_ah;
    int n  = blockIdx.y;
    int l0 = blockIdx.x * 128;
    int tid = threadIdx.x;

    const float* srcn = src + n * CC * LL;
    // load phase: 8 iters x (8 rows x 128 floats), each LDG = full 128B line
    {
        int c0 = tid >> 5;            // 0..7
        int col = (tid & 31) * 4;
        #pragma unroll
        for (int it = 0; it < 8; ++it) {
            int c = it * 8 + c0;
            float4 v = *(const float4*)(srcn + c * LL + l0 + col);
            *(float4*)&xs[c][col] = v;
        }
    }
    __syncthreads();

    // compute phase: 2 threads per pixel, 32 channels each
    int l = tid >> 1;                 // 0..127
    int h = tid & 1;                  // channel half
    float x[32]; float ss = 0.f;
    #pragma unroll
    for (int c = 0; c < 32; ++c) {
        float v = xs[h * 32 + c][l];
        x[c] = v; ss += v * v;
    }
    ss += __shfl_xor_sync(0xffffffffu, ss, 1);
    float sc = 3.79828262f / fmaxf(sqrtf(ss), 1e-12f);   // sqrt(10*log2(e))

    unsigned u[16];
    #pragma unroll
    for (int k = 0; k < 16; ++k) {
        __half2 h2 = __floats2half2_rn(x[2*k] * sc, x[2*k+1] * sc);
        u[k] = *reinterpret_cast<unsigned*>(&h2);
    }
    uint4* pd = (uint4*)dst + (size_t)(n * LL + l0 + l) * 8 + h * 4;
    pd[0] = make_uint4(u[0],  u[1],  u[2],  u[3]);
    pd[1] = make_uint4(u[4],  u[5],  u[6],  u[7]);
    pd[2] = make_uint4(u[8],  u[9],  u[10], u[11]);
    pd[3] = make_uint4(u[12], u[13], u[14], u[15]);
}

// ---------------- kernel 2: HMMA (mma.sync fp16) + fused stats ---------------
// grid (8 i-panels, 32 n, 8 j-chunks); each CTA: one 128x128 tile
#define OA    0         // 16384
#define OB    16384     // 16384
#define OCK   32768     // u64[8][128] = 8192
#define OCS   40960     // f32[8][128] = 4096
#define ORK   45056     // u64[2][128] = 2048
#define ORS   47104     // f32[2][128] = 1024
#define SMEM_BYTES 48128

__global__ __launch_bounds__(256, 2) void mma_stats_kernel() {
    extern __shared__ __align__(16) char sm[];
    uint32_t sb = smem_u32(sm);

    int tid  = threadIdx.x;
    int lane = tid & 31;
    int wid  = tid >> 5;
    int wm = wid & 3, wn = wid >> 2;          // 4 m-slices x 2 n-slices
    int m0 = wm * 32;
    int n  = blockIdx.y;
    int i0 = blockIdx.x * 128;
    int qz = blockIdx.z;                      // j-chunk
    int j0 = qz * 128;

    unsigned long long* colkey = (unsigned long long*)(sm + OCK);
    float*              colsum = (float*)(sm + OCS);
    unsigned long long* rowkey = (unsigned long long*)(sm + ORK);
    float*              rowsum = (float*)(sm + ORS);

    // load A and B tiles: 128 rows x 128B, SW128-swizzled
    {
        const uint4* sA = (const uint4*)g_ah + (size_t)(n * LL + i0) * 8;
        const uint4* sB = (const uint4*)g_bh + (size_t)(n * LL + j0) * 8;
        int sub = tid & 7, rb = tid >> 3;
        #pragma unroll
        for (int p = 0; p < 4; ++p) {
            int row = p * 32 + rb;
            uint32_t off = SW128((uint32_t)(row * 128 + sub * 16));
            *(uint4*)(sm + OA + off) = sA[row * 8 + sub];
            *(uint4*)(sm + OB + off) = sB[row * 8 + sub];
        }
    }
    __syncthreads();

    int lr = lane >> 2, lc2 = (lane & 3) * 2;

    float rm[4], rs[4]; int rj[4];
    #pragma unroll
    for (int r = 0; r < 4; ++r) { rm[r] = 0.f; rs[r] = 0.f; rj[r] = 0; }

    float acc[2][8][4];
    #pragma unroll
    for (int mt = 0; mt < 2; ++mt)
        #pragma unroll
        for (int nt = 0; nt < 8; ++nt)
            #pragma unroll
            for (int k = 0; k < 4; ++k) acc[mt][nt][k] = 0.f;

    #pragma unroll
    for (int kk = 0; kk < 4; ++kk) {
        uint32_t afr[2][4], bfr[4][4];
        #pragma unroll
        for (int mt = 0; mt < 2; ++mt) {
            uint32_t off = SW128((uint32_t)((m0 + mt * 16 + (lane & 15)) * 128
                                            + kk * 32 + (lane >> 4) * 16));
            ldmx4(afr[mt], sb + OA + off);
        }
        #pragma unroll
        for (int np = 0; np < 4; ++np) {
            uint32_t off = SW128((uint32_t)((wn * 64 + np * 16 + (lane & 15)) * 128
                                            + kk * 32 + (lane >> 4) * 16));
            ldmx4(bfr[np], sb + OB + off);
        }
        #pragma unroll
        for (int mt = 0; mt < 2; ++mt)
            #pragma unroll
            for (int np = 0; np < 4; ++np) {
                mma16816(acc[mt][2*np],   afr[mt], bfr[np][0], bfr[np][2]);
                mma16816(acc[mt][2*np+1], afr[mt], bfr[np][1], bfr[np][3]);
            }
    }

    // ---- epilogue: 2^x in place + per-thread row stats ----
    #pragma unroll
    for (int mt = 0; mt < 2; ++mt)
        #pragma unroll
        for (int h = 0; h < 2; ++h) {
            int rid = mt * 2 + h;
            #pragma unroll
            for (int nt = 0; nt < 8; ++nt)
                #pragma unroll
                for (int e = 0; e < 2; ++e) {
                    float v = ex2f(acc[mt][nt][h * 2 + e]);
                    acc[mt][nt][h * 2 + e] = v;
                    rs[rid] += v;
                    int j = j0 + wn * 64 + nt * 8 + lc2 + e;
                    if (v > rm[rid]) { rm[rid] = v; rj[rid] = j; }
                }
        }

    // ---- col partials: 4 local rows, then 2 shuffle rounds (8 groups) ----
    #pragma unroll
    for (int nt = 0; nt < 8; ++nt)
        #pragma unroll
        for (int e = 0; e < 2; ++e) {
            float v0 = acc[0][nt][e],     v1 = acc[0][nt][2 + e];
            float v2 = acc[1][nt][e],     v3 = acc[1][nt][2 + e];
            float cs = v0; cs += v1; cs += v2; cs += v3;
            float cm = v0; int ri = 0;                 // rows asc: +0,+8,+16,+24
            if (v1 > cm) { cm = v1; ri = 1; }
            if (v2 > cm) { cm = v2; ri = 2; }
            if (v3 > cm) { cm = v3; ri = 3; }
            int grow = i0 + m0 + (ri >> 1) * 16 + (ri & 1) * 8 + lr;
            unsigned long long key =
                ((unsigned long long)__float_as_uint(cm) << 32) |
                (unsigned)(0xFFFFFFFFu - (unsigned)grow);
            #pragma unroll
            for (int off = 16; off >= 8; off >>= 1) {
                unsigned long long ko = __shfl_down_sync(0xffffffffu, key, off);
                float so = __shfl_down_sync(0xffffffffu, cs, off);
                cs += so;
                if (ko > key) key = ko;
            }
            if (lane < 8) {
                int g = wm * 2 + (lane >> 2);          // 8 groups
                int col = wn * 64 + nt * 8 + lc2 + e;
                colkey[g * 128 + col] = key;
                colsum[g * 128 + col] = cs;
            }
        }
    __syncthreads();
    if (tid < 128) {   // merge 8 group partials in fixed order
        unsigned long long key = colkey[tid];
        float sum = colsum[tid];
        #pragma unroll
        for (int g = 1; g < 8; ++g) {
            unsigned long long ko = colkey[g * 128 + tid];
            if (ko > key) key = ko;
            sum += colsum[g * 128 + tid];
        }
        g_ckey[blockIdx.x][n * LL + j0 + tid] = key;
        g_csum[blockIdx.x][n * LL + j0 + tid] = sum;
    }

    // ---- row partials for this chunk: 4-lane tree, wn merge, write ----------
    #pragma unroll
    for (int off = 2; off >= 1; off >>= 1) {
        #pragma unroll
        for (int r = 0; r < 4; ++r) {
            float mo = __shfl_down_sync(0xffffffffu, rm[r], off);
            int   jo = __shfl_down_sync(0xffffffffu, rj[r], off);
            float so = __shfl_down_sync(0xffffffffu, rs[r], off);
            rs[r] += so;
            if (mo > rm[r] || (mo == rm[r] && jo < rj[r])) { rm[r] = mo; rj[r] = jo; }
        }
    }
    __syncthreads();   // colkey merge done; rowkey region free
    if ((lane & 3) == 0) {
        #pragma unroll
        for (int r = 0; r < 4; ++r) {
            int row = m0 + (r >> 1) * 16 + (r & 1) * 8 + lr;
            rowkey[wn * 128 + row] =
                ((unsigned long long)__float_as_uint(rm[r]) << 32) |
                (unsigned)(0xFFFFFFFFu - (unsigned)rj[r]);
            rowsum[wn * 128 + row] = rs[r];
        }
    }
    __syncthreads();
    if (tid < 128) {
        unsigned long long k0 = rowkey[tid], k1 = rowkey[128 + tid];
        float s = rowsum[tid] + rowsum[128 + tid];
        unsigned long long k = (k1 > k0) ? k1 : k0;
        int gi = n * LL + i0 + tid;
        g_rkey[qz][gi] = k;
        g_rsum[qz][gi] = s;
    }
}

// ---------------- kernel 3: merge partials + -log terms + final reduce -------
// reference: max_h/(sum_h + eps) * max_o[arg_h] / (sum_o + eps); sum_o at OWN index.
__device__ __forceinline__ unsigned long long row_key(int i) {
    unsigned long long key = g_rkey[0][i];
    #pragma unroll
    for (int q = 1; q < 8; ++q) { unsigned long long k = g_rkey[q][i]; if (k > key) key = k; }
    return key;
}
__device__ __forceinline__ float row_sum(int i) {
    float s = g_rsum[0][i];
    #pragma unroll
    for (int q = 1; q < 8; ++q) s += g_rsum[q][i];
    return s;
}
__device__ __forceinline__ unsigned long long col_key(int i) {
    unsigned long long key = g_ckey[0][i];
    #pragma unroll
    for (int b = 1; b < 8; ++b) { unsigned long long k = g_ckey[b][i]; if (k > key) key = k; }
    return key;
}
__device__ __forceinline__ float col_sum(int i) {
    float s = g_csum[0][i];
    #pragma unroll
    for (int b = 1; b < 8; ++b) s += g_csum[b][i];
    return s;
}

__global__ void loss_kernel(float* __restrict__ out) {   // grid 256 x 256
    int ee = blockIdx.x * 256 + threadIdx.x;   // 0..65535
    int half = ee >> 15;                       // 0: rgb2ir2rgb, 1: ir2rgb2ir
    int idx  = ee & 32767;                     // n*L + l
    int base = idx & ~(LL - 1);
    float mp, sp, mo, so;

    if (half == 0) {
        unsigned long long rk = row_key(idx);
        mp = __uint_as_float((unsigned)(rk >> 32));
        sp = row_sum(idx);
        int a = (int)(0xFFFFFFFFu - (unsigned)(rk & 0xFFFFFFFFu)) & (LL - 1);
        mo = __uint_as_float((unsigned)(col_key(base + a) >> 32));
        so = col_sum(idx);
    } else {
        unsigned long long ck = col_key(idx);
        mp = __uint_as_float((unsigned)(ck >> 32));
        sp = col_sum(idx);
        int a = (int)(0xFFFFFFFFu - (unsigned)(ck & 0xFFFFFFFFu)) & (LL - 1);
        mo = __uint_as_float((unsigned)(row_key(base + a) >> 32));
        so = row_sum(idx);
    }
    float acc = __logf(mp / (sp + EPS) * (mo / (so + EPS)));

    __shared__ float red[256];
    __shared__ unsigned is_last;
    red[threadIdx.x] = acc;
    __syncthreads();
    for (int st = 128; st; st >>= 1) {
        if (threadIdx.x < st) red[threadIdx.x] += red[threadIdx.x + st];
        __syncthreads();
    }
    if (threadIdx.x == 0) {
        g_part[blockIdx.x] = red[0];
        __threadfence();
        is_last = (atomicAdd(&g_cnt, 1u) == 255u) ? 1u : 0u;
    }
    __syncthreads();
    if (is_last) {
        __threadfence();
        red[threadIdx.x] = __ldcg(&g_part[threadIdx.x]);
        __syncthreads();
        for (int st = 128; st; st >>= 1) {
            if (threadIdx.x < st) red[threadIdx.x] += red[threadIdx.x + st];
            __syncthreads();
        }
        if (threadIdx.x == 0) {
            out[0] = -red[0] * (1.0f / 65536.0f);
            g_cnt = 0;                      // reset for graph replay
        }
    }
}

// ---------------- launch ------------------------------------------------------
extern "C" void kernel_launch(void* const* d_in, const int* in_sizes, int n_in,
                              void* d_out, int out_size) {
    const float* rgb = (const float*)d_in[0];
    const float* ir  = (const float*)d_in[1];

    cudaFuncSetAttribute(mma_stats_kernel,
                         cudaFuncAttributeMaxDynamicSharedMemorySize, SMEM_BYTES);

    prep_kernel<<<dim3(8, 32, 2), 256>>>(rgb, ir);
    mma_stats_kernel<<<dim3(8, 32, 8), 256, SMEM_BYTES>>>();
    loss_kernel<<<256, 256>>>((float*)d_out);
}